// round 1
// baseline (speedup 1.0000x reference)
#include <cuda_runtime.h>
#include <math.h>

#define DEV_EPS 0.025f

// ---------------- device scratch (no allocations allowed) ----------------
__device__ float g_Wt[4096 * 64];        // transposed conv1 weights: [k][ch]
__device__ float g_part[4 * 4096 * 64];  // k-split GEMM partials [kz][patch][ch]
__device__ float g_pt[4 * 4096];         // k-split tconv partials
__device__ float g_s[4096];              // channel-summed metric per patch
__device__ float g_tt[4096];             // DEV_EPS + t per patch
__device__ float g_scale1[64];
__device__ float g_shift1[64];
__device__ float g_w2[64];
__device__ float g_misc[4];              // [0]=b2 [1]=scale_t [2]=shift_t

// ---------------- prep: transpose conv1 weights to [k][ch] ----------------
__global__ void prep_wt_kernel(const float* __restrict__ conv1_w) {
    int idx = blockIdx.x * blockDim.x + threadIdx.x;
    for (; idx < 4096 * 64; idx += gridDim.x * blockDim.x) {
        int k = idx >> 6, ch = idx & 63;
        g_Wt[idx] = conv1_w[ch * 4096 + k];
    }
}

// ---------------- prep: BN folding + conv2 channel-sum ----------------
__global__ void prep_small_kernel(const float* __restrict__ conv1_b,
                                  const float* __restrict__ bn1_g,
                                  const float* __restrict__ bn1_b,
                                  const float* __restrict__ bn1_m,
                                  const float* __restrict__ bn1_v,
                                  const float* __restrict__ conv2_w,
                                  const float* __restrict__ conv2_b,
                                  const float* __restrict__ tconv_b,
                                  const float* __restrict__ bnt_g,
                                  const float* __restrict__ bnt_b,
                                  const float* __restrict__ bnt_m,
                                  const float* __restrict__ bnt_v) {
    int ch = threadIdx.x;
    if (ch < 64) {
        float inv = 1.0f / sqrtf(bn1_v[ch] + 1e-5f);
        float sc = bn1_g[ch] * inv;
        g_scale1[ch] = sc;
        g_shift1[ch] = sc * (conv1_b[ch] - bn1_m[ch]) + bn1_b[ch];
        float w2 = 0.f;
        for (int cl = 0; cl < 64; ++cl) w2 += conv2_w[cl * 64 + ch];
        g_w2[ch] = w2;
    }
    if (ch == 0) {
        float b2 = 0.f;
        for (int cl = 0; cl < 64; ++cl) b2 += conv2_b[cl];
        g_misc[0] = b2;
        float it = 1.0f / sqrtf(bnt_v[0] + 1e-5f);
        float st = bnt_g[0] * it;
        g_misc[1] = st;
        g_misc[2] = st * (tconv_b[0] - bnt_m[0]) + bnt_b[0];
    }
}

// ---------------- patch GEMM: 4096 patches x 64 ch (+tconv), K=4096, split 4 ----------------
// Block: 128 patches x 64 channels x 1024-K slice. Grid (32, 4). 256 threads.
// Thread micro-tile: 8 patches x 4 channels.
__global__ __launch_bounds__(256) void gemm_kernel(const float* __restrict__ x,
                                                   const float* __restrict__ tw) {
    __shared__ float As[32 * 128];  // [kk][patch]
    __shared__ float Ws[32 * 64];   // [kk][ch]
    __shared__ float tws[32];

    const int tid = threadIdx.x;
    const int pbase = blockIdx.x * 128;
    const int kz = blockIdx.y;
    const int pg = tid >> 4;   // 0..15 -> patches pg*8..pg*8+7
    const int cg = tid & 15;   // 0..15 -> channels cg*4..cg*4+3

    // A-load assignment: u = tid + 256*r covers (m=u>>7 in 0..7, patch=u&127).
    // float4 along kx: k = koff + 4m -> row = py*8 + kyb + (m>>1), col = px*8 + (m&1)*4
    int aoff[4], sb[4];
#pragma unroll
    for (int r = 0; r < 4; ++r) {
        int u = tid + 256 * r;
        int m = u >> 7;
        int pat = u & 127;
        int p = pbase + pat;
        int bb = p >> 10, py = (p >> 5) & 31, px = p & 31;
        aoff[r] = (bb << 22) + (py << 11) + (px << 3) + ((m >> 1) << 8) + ((m & 1) << 2);
        sb[r] = (m << 9) + pat;  // (m*4)*128 + patch
    }

    float acc[8][4];
#pragma unroll
    for (int i = 0; i < 8; ++i)
#pragma unroll
        for (int j = 0; j < 4; ++j) acc[i][j] = 0.f;
    float tacc[8];
#pragma unroll
    for (int i = 0; i < 8; ++i) tacc[i] = 0.f;

    for (int cc = 0; cc < 32; ++cc) {
        const int koff = kz * 1024 + cc * 32;
        const int cin = koff >> 6;
        const int kyb = (koff >> 3) & 7;
        const int xoff = (cin << 16) + (kyb << 8);
#pragma unroll
        for (int r = 0; r < 4; ++r) {
            float4 v = *(const float4*)(x + aoff[r] + xoff);
            int s = sb[r];
            As[s] = v.x;
            As[s + 128] = v.y;
            As[s + 256] = v.z;
            As[s + 384] = v.w;
        }
#pragma unroll
        for (int r = 0; r < 2; ++r) {
            int u = tid + 256 * r;
            ((float4*)Ws)[u] = ((const float4*)(g_Wt + (size_t)koff * 64))[u];
        }
        if (tid < 8) ((float4*)tws)[tid] = ((const float4*)(tw + koff))[tid];
        __syncthreads();

#pragma unroll
        for (int kk = 0; kk < 32; ++kk) {
            float4 a0 = *(const float4*)&As[kk * 128 + pg * 8];
            float4 a1 = *(const float4*)&As[kk * 128 + pg * 8 + 4];
            float4 w = *(const float4*)&Ws[kk * 64 + cg * 4];
            float a[8] = {a0.x, a0.y, a0.z, a0.w, a1.x, a1.y, a1.z, a1.w};
#pragma unroll
            for (int i = 0; i < 8; ++i) {
                acc[i][0] = fmaf(a[i], w.x, acc[i][0]);
                acc[i][1] = fmaf(a[i], w.y, acc[i][1]);
                acc[i][2] = fmaf(a[i], w.z, acc[i][2]);
                acc[i][3] = fmaf(a[i], w.w, acc[i][3]);
            }
            if (cg == 0) {
                float twk = tws[kk];
#pragma unroll
                for (int i = 0; i < 8; ++i) tacc[i] = fmaf(a[i], twk, tacc[i]);
            }
        }
        __syncthreads();
    }

#pragma unroll
    for (int i = 0; i < 8; ++i) {
        int p = pbase + pg * 8 + i;
        float4 o;
        o.x = acc[i][0]; o.y = acc[i][1]; o.z = acc[i][2]; o.w = acc[i][3];
        *(float4*)&g_part[((size_t)(kz * 4096 + p)) * 64 + cg * 4] = o;
    }
    if (cg == 0) {
#pragma unroll
        for (int i = 0; i < 8; ++i) g_pt[kz * 4096 + pbase + pg * 8 + i] = tacc[i];
    }
}

// ---------------- epilogue: k-split reduce + BN + ReLU + channel reduce ----------------
__global__ __launch_bounds__(256) void epi_kernel() {
    int p = blockIdx.x * 8 + (threadIdx.x >> 5);
    int lane = threadIdx.x & 31;
    float y0 = 0.f, y1 = 0.f;
#pragma unroll
    for (int kz = 0; kz < 4; ++kz) {
        const float* base = g_part + ((size_t)(kz * 4096 + p)) * 64;
        y0 += base[lane];
        y1 += base[lane + 32];
    }
    float v = fmaxf(fmaf(g_scale1[lane], y0, g_shift1[lane]), 0.f) * g_w2[lane] +
              fmaxf(fmaf(g_scale1[lane + 32], y1, g_shift1[lane + 32]), 0.f) * g_w2[lane + 32];
#pragma unroll
    for (int o = 16; o; o >>= 1) v += __shfl_xor_sync(0xffffffffu, v, o);
    if (lane == 0) {
        g_s[p] = v + g_misc[0];
        float ty = 0.f;
#pragma unroll
        for (int kz = 0; kz < 4; ++kz) ty += g_pt[kz * 4096 + p];
        float t = fmaxf(fmaf(g_misc[1], ty, g_misc[2]), 0.f);
        g_tt[p] = DEV_EPS + t;
    }
}

// ---------------- softmax pipeline ----------------
__device__ __forceinline__ float bred_max(float v, float* sh) {
#pragma unroll
    for (int o = 16; o; o >>= 1) v = fmaxf(v, __shfl_xor_sync(0xffffffffu, v, o));
    __syncthreads();
    if ((threadIdx.x & 31) == 0) sh[threadIdx.x >> 5] = v;
    __syncthreads();
    float r = sh[0];
#pragma unroll
    for (int k = 1; k < 8; ++k) r = fmaxf(r, sh[k]);
    return r;
}

__device__ __forceinline__ float bred_sum(float v, float* sh) {
#pragma unroll
    for (int o = 16; o; o >>= 1) v += __shfl_xor_sync(0xffffffffu, v, o);
    __syncthreads();
    if ((threadIdx.x & 31) == 0) sh[threadIdx.x >> 5] = v;
    __syncthreads();
    float r = sh[0];
#pragma unroll
    for (int k = 1; k < 8; ++k) r += sh[k];
    return r;
}

__global__ __launch_bounds__(256) void softmax_kernel(float* __restrict__ out) {
    __shared__ float sh[8];
    const int r = blockIdx.x;
    const int b = r >> 10, i = r & 1023;
    const float si = g_s[r];
    const float invt = 1.0f / g_tt[r];
    float4 s4 = ((const float4*)(g_s + (b << 10)))[threadIdx.x];
    const int j0 = threadIdx.x << 2;
    float sv[4] = {s4.x, s4.y, s4.z, s4.w};
    float l[4];
#pragma unroll
    for (int q = 0; q < 4; ++q) {
        float d = si - sv[q];
        float val = -d * d;
        if (j0 + q == i) val -= 1000.0f;
        l[q] = val * invt;
    }
    const size_t obase = ((size_t)b << 20) + ((size_t)i << 10) + j0;
#pragma unroll 1
    for (int it = 0; it < 4; ++it) {
        float m = fmaxf(fmaxf(l[0], l[1]), fmaxf(l[2], l[3]));
        m = bred_max(m, sh);
        float e[4];
        float ls = 0.f;
#pragma unroll
        for (int q = 0; q < 4; ++q) {
            e[q] = expf(l[q] - m);
            ls += e[q];
        }
        float S = bred_sum(ls, sh);
        float p[4];
#pragma unroll
        for (int q = 0; q < 4; ++q) p[q] = e[q] / S;  // true div: guarantees p <= 1
        float4 po;
        po.x = p[0]; po.y = p[1]; po.z = p[2]; po.w = p[3];
        *(float4*)(out + obase + ((size_t)it << 22)) = po;
        if (it < 3) {
#pragma unroll
            for (int q = 0; q < 4; ++q) {
                float om = (1.0f - p[q]) + 1e-45f;
                l[q] += logf(om) * invt;
            }
        }
    }
}

// ---------------- launch ----------------
extern "C" void kernel_launch(void* const* d_in, const int* in_sizes, int n_in,
                              void* d_out, int out_size) {
    const float* x = (const float*)d_in[0];
    const float* conv1_w = (const float*)d_in[1];
    const float* conv1_b = (const float*)d_in[2];
    const float* bn1_g = (const float*)d_in[3];
    const float* bn1_b = (const float*)d_in[4];
    const float* bn1_m = (const float*)d_in[5];
    const float* bn1_v = (const float*)d_in[6];
    const float* conv2_w = (const float*)d_in[7];
    const float* conv2_b = (const float*)d_in[8];
    const float* tconv_w = (const float*)d_in[9];
    const float* tconv_b = (const float*)d_in[10];
    const float* bnt_g = (const float*)d_in[11];
    const float* bnt_b = (const float*)d_in[12];
    const float* bnt_m = (const float*)d_in[13];
    const float* bnt_v = (const float*)d_in[14];
    float* out = (float*)d_out;

    prep_wt_kernel<<<256, 256>>>(conv1_w);
    prep_small_kernel<<<1, 64>>>(conv1_b, bn1_g, bn1_b, bn1_m, bn1_v,
                                 conv2_w, conv2_b, tconv_b, bnt_g, bnt_b, bnt_m, bnt_v);
    dim3 g(32, 4);
    gemm_kernel<<<g, 256>>>(x, tconv_w);
    epi_kernel<<<512, 256>>>();
    softmax_kernel<<<4096, 256>>>(out);
}

// round 2
// speedup vs baseline: 2.1739x; 2.1739x over previous
#include <cuda_runtime.h>
#include <math.h>

#define DEV_EPS 0.025f

// ---------------- device scratch ----------------
__device__ float g_Wt[4096 * 64];        // transposed conv1 weights: [k][ch]
__device__ float g_part[8 * 4096 * 64];  // k-split GEMM partials [kz][patch][ch]
__device__ float g_s[4096];              // channel-summed metric per patch
__device__ float g_tt[4096];             // DEV_EPS + t per patch
__device__ float g_scale1[64];
__device__ float g_shift1[64];
__device__ float g_w2[64];
__device__ float g_misc[4];              // [0]=b2 [1]=scale_t [2]=shift_t

__device__ __forceinline__ float ex2a(float x) {
    float y; asm("ex2.approx.ftz.f32 %0, %1;" : "=f"(y) : "f"(x)); return y;
}
__device__ __forceinline__ float lg2a(float x) {
    float y; asm("lg2.approx.f32 %0, %1;" : "=f"(y) : "f"(x)); return y;
}

// ---------------- prep: transpose conv1 weights to [k][ch] ----------------
__global__ void prep_wt_kernel(const float* __restrict__ conv1_w) {
    int idx = blockIdx.x * blockDim.x + threadIdx.x;
    for (; idx < 4096 * 64; idx += gridDim.x * blockDim.x) {
        int k = idx >> 6, ch = idx & 63;
        g_Wt[idx] = conv1_w[ch * 4096 + k];
    }
}

// ---------------- prep: BN folding + conv2 channel-sum ----------------
__global__ void prep_small_kernel(const float* __restrict__ conv1_b,
                                  const float* __restrict__ bn1_g,
                                  const float* __restrict__ bn1_b,
                                  const float* __restrict__ bn1_m,
                                  const float* __restrict__ bn1_v,
                                  const float* __restrict__ conv2_w,
                                  const float* __restrict__ conv2_b,
                                  const float* __restrict__ tconv_b,
                                  const float* __restrict__ bnt_g,
                                  const float* __restrict__ bnt_b,
                                  const float* __restrict__ bnt_m,
                                  const float* __restrict__ bnt_v) {
    int ch = threadIdx.x;
    if (ch < 64) {
        float inv = 1.0f / sqrtf(bn1_v[ch] + 1e-5f);
        float sc = bn1_g[ch] * inv;
        g_scale1[ch] = sc;
        g_shift1[ch] = sc * (conv1_b[ch] - bn1_m[ch]) + bn1_b[ch];
        float w2 = 0.f;
        for (int cl = 0; cl < 64; ++cl) w2 += conv2_w[cl * 64 + ch];
        g_w2[ch] = w2;
    }
    if (ch == 0) {
        float b2 = 0.f;
        for (int cl = 0; cl < 64; ++cl) b2 += conv2_b[cl];
        g_misc[0] = b2;
        float it = 1.0f / sqrtf(bnt_v[0] + 1e-5f);
        float st = bnt_g[0] * it;
        g_misc[1] = st;
        g_misc[2] = st * (tconv_b[0] - bnt_m[0]) + bnt_b[0];
    }
}

// ---------------- temperature head: matvec over K=4096 per patch ----------------
__global__ __launch_bounds__(128) void tvec_kernel(const float* __restrict__ x,
                                                   const float* __restrict__ tw) {
    __shared__ float sh[4];
    const int p = blockIdx.x;
    const int b = p >> 10, py = (p >> 5) & 31, px = p & 31;
    const float* xp = x + ((size_t)b << 22) + (py << 11) + (px << 3);
    const int t = threadIdx.x;
    float acc = 0.f;
#pragma unroll
    for (int r = 0; r < 8; ++r) {
        int u = t + 128 * r;  // 0..1023
        int cin = u >> 4, ky = (u >> 1) & 7, kxh = u & 1;
        float4 v = *(const float4*)(xp + (cin << 16) + (ky << 8) + (kxh << 2));
        float4 w = *(const float4*)(tw + (u << 2));
        acc += v.x * w.x + v.y * w.y + v.z * w.z + v.w * w.w;
    }
#pragma unroll
    for (int o = 16; o; o >>= 1) acc += __shfl_xor_sync(0xffffffffu, acc, o);
    if ((t & 31) == 0) sh[t >> 5] = acc;
    __syncthreads();
    if (t == 0) {
        float y = sh[0] + sh[1] + sh[2] + sh[3];
        float tv = fmaxf(fmaf(g_misc[1], y, g_misc[2]), 0.f);
        g_tt[p] = DEV_EPS + tv;
    }
}

// ---------------- patch GEMM: tile 256 patches x 64 ch, K split 8 (512 each) ----------------
// Grid (16, 8), 256 threads. Micro-tile 8 patches x 8 channels. Reg-prefetch double buffer.
__global__ __launch_bounds__(256) void gemm_kernel(const float* __restrict__ x) {
    __shared__ float As[32 * 256];  // [k_local][patch]
    __shared__ float Ws[32 * 64];   // [k_local][ch]

    const int tid = threadIdx.x;
    const int pbase = blockIdx.x << 8;
    const int kz = blockIdx.y;
    const int pg = tid >> 3;  // 0..31 -> patches pg*8..+7
    const int cg = tid & 7;   // 0..7  -> channels cg*8..+7

    // A-load: this thread loads all 32 k's of chunk for patch pbase+tid
    const int p = pbase + tid;
    const int b = p >> 10, py = (p >> 5) & 31, px = p & 31;
    const float* xp = x + ((size_t)b << 22) + (py << 11) + (px << 3);

    float acc[8][8];
#pragma unroll
    for (int i = 0; i < 8; ++i)
#pragma unroll
        for (int j = 0; j < 8; ++j) acc[i][j] = 0.f;

    float4 pa[8], pw[2];
    int koff = kz << 9;
    // prefetch chunk 0
    {
        const int cin = koff >> 6, kyb = (koff >> 3) & 7;
        const float* xc = xp + (cin << 16) + (kyb << 8);
#pragma unroll
        for (int m = 0; m < 8; ++m)
            pa[m] = *(const float4*)(xc + ((m >> 1) << 8) + ((m & 1) << 2));
        const float4* wg = (const float4*)(g_Wt + (size_t)koff * 64);
        pw[0] = wg[tid];
        pw[1] = wg[tid + 256];
    }

    for (int cc = 0; cc < 16; ++cc) {
        __syncthreads();
#pragma unroll
        for (int m = 0; m < 8; ++m) {
            int kl = ((m >> 1) << 3) + ((m & 1) << 2);
            As[(kl + 0) * 256 + tid] = pa[m].x;
            As[(kl + 1) * 256 + tid] = pa[m].y;
            As[(kl + 2) * 256 + tid] = pa[m].z;
            As[(kl + 3) * 256 + tid] = pa[m].w;
        }
        ((float4*)Ws)[tid] = pw[0];
        ((float4*)Ws)[tid + 256] = pw[1];
        __syncthreads();

        if (cc < 15) {
            const int k2 = koff + 32;
            const int cin = k2 >> 6, kyb = (k2 >> 3) & 7;
            const float* xc = xp + (cin << 16) + (kyb << 8);
#pragma unroll
            for (int m = 0; m < 8; ++m)
                pa[m] = *(const float4*)(xc + ((m >> 1) << 8) + ((m & 1) << 2));
            const float4* wg = (const float4*)(g_Wt + (size_t)k2 * 64);
            pw[0] = wg[tid];
            pw[1] = wg[tid + 256];
        }

#pragma unroll 4
        for (int kk = 0; kk < 32; ++kk) {
            float4 a0 = *(const float4*)&As[kk * 256 + pg * 8];
            float4 a1 = *(const float4*)&As[kk * 256 + pg * 8 + 4];
            float4 w0 = *(const float4*)&Ws[kk * 64 + cg * 8];
            float4 w1 = *(const float4*)&Ws[kk * 64 + cg * 8 + 4];
            float a[8] = {a0.x, a0.y, a0.z, a0.w, a1.x, a1.y, a1.z, a1.w};
            float w[8] = {w0.x, w0.y, w0.z, w0.w, w1.x, w1.y, w1.z, w1.w};
#pragma unroll
            for (int i = 0; i < 8; ++i)
#pragma unroll
                for (int j = 0; j < 8; ++j) acc[i][j] = fmaf(a[i], w[j], acc[i][j]);
        }
        koff += 32;
    }

#pragma unroll
    for (int i = 0; i < 8; ++i) {
        int p2 = pbase + pg * 8 + i;
        float* dst = g_part + ((size_t)(kz * 4096 + p2)) * 64 + cg * 8;
        float4 o0, o1;
        o0.x = acc[i][0]; o0.y = acc[i][1]; o0.z = acc[i][2]; o0.w = acc[i][3];
        o1.x = acc[i][4]; o1.y = acc[i][5]; o1.z = acc[i][6]; o1.w = acc[i][7];
        *(float4*)dst = o0;
        *(float4*)(dst + 4) = o1;
    }
}

// ---------------- epilogue: k-split reduce + BN + ReLU + channel reduce ----------------
__global__ __launch_bounds__(256) void epi_kernel() {
    int p = blockIdx.x * 8 + (threadIdx.x >> 5);
    int lane = threadIdx.x & 31;
    float y0 = 0.f, y1 = 0.f;
#pragma unroll
    for (int kz = 0; kz < 8; ++kz) {
        const float* base = g_part + ((size_t)(kz * 4096 + p)) * 64;
        y0 += base[lane];
        y1 += base[lane + 32];
    }
    float v = fmaxf(fmaf(g_scale1[lane], y0, g_shift1[lane]), 0.f) * g_w2[lane] +
              fmaxf(fmaf(g_scale1[lane + 32], y1, g_shift1[lane + 32]), 0.f) * g_w2[lane + 32];
#pragma unroll
    for (int o = 16; o; o >>= 1) v += __shfl_xor_sync(0xffffffffu, v, o);
    if (lane == 0) g_s[p] = v + g_misc[0];
}

// ---------------- softmax: warp-per-row, register logits, MUFU fast path ----------------
__global__ __launch_bounds__(256) void softmax_kernel(float* __restrict__ out) {
    const int w = threadIdx.x >> 5, lane = threadIdx.x & 31;
    const int r = blockIdx.x * 8 + w;
    const int b = r >> 10, i = r & 1023;
    const float si = g_s[r];
    const float invt = 1.0f / g_tt[r];
    const float c = invt * 1.4426950408889634f;  // invt * log2(e)

    float l2[32];
#pragma unroll
    for (int q = 0; q < 8; ++q) {
        int j = (q << 7) + (lane << 2);
        float4 s4 = *(const float4*)(g_s + (b << 10) + j);
        float sv[4] = {s4.x, s4.y, s4.z, s4.w};
#pragma unroll
        for (int u = 0; u < 4; ++u) {
            float d = si - sv[u];
            float val = -d * d;
            if (j + u == i) val -= 1000.0f;
            l2[q * 4 + u] = val * c;
        }
    }

    const size_t rbase = ((size_t)b << 20) + ((size_t)i << 10);
#pragma unroll 1
    for (int it = 0; it < 4; ++it) {
        float m = l2[0];
#pragma unroll
        for (int q = 1; q < 32; ++q) m = fmaxf(m, l2[q]);
#pragma unroll
        for (int o = 16; o; o >>= 1) m = fmaxf(m, __shfl_xor_sync(0xffffffffu, m, o));
        float e[32];
        float s = 0.f;
#pragma unroll
        for (int q = 0; q < 32; ++q) {
            e[q] = ex2a(l2[q] - m);
            s += e[q];
        }
#pragma unroll
        for (int o = 16; o; o >>= 1) s += __shfl_xor_sync(0xffffffffu, s, o);
        float invS = 1.0f / s;
        float* op = out + (((size_t)it) << 22) + rbase + (lane << 2);
#pragma unroll
        for (int q = 0; q < 8; ++q) {
            float4 po;
            po.x = e[q * 4 + 0] * invS;
            po.y = e[q * 4 + 1] * invS;
            po.z = e[q * 4 + 2] * invS;
            po.w = e[q * 4 + 3] * invS;
            *(float4*)(op + (q << 7)) = po;
        }
        if (it < 3) {
#pragma unroll
            for (int q = 0; q < 32; ++q) {
                float pr = e[q] * invS;
                float om = fmaxf(1.0f - pr, 1e-38f);
                l2[q] += lg2a(om) * invt;
            }
        }
    }
}

// ---------------- launch ----------------
extern "C" void kernel_launch(void* const* d_in, const int* in_sizes, int n_in,
                              void* d_out, int out_size) {
    const float* x = (const float*)d_in[0];
    const float* conv1_w = (const float*)d_in[1];
    const float* conv1_b = (const float*)d_in[2];
    const float* bn1_g = (const float*)d_in[3];
    const float* bn1_b = (const float*)d_in[4];
    const float* bn1_m = (const float*)d_in[5];
    const float* bn1_v = (const float*)d_in[6];
    const float* conv2_w = (const float*)d_in[7];
    const float* conv2_b = (const float*)d_in[8];
    const float* tconv_w = (const float*)d_in[9];
    const float* tconv_b = (const float*)d_in[10];
    const float* bnt_g = (const float*)d_in[11];
    const float* bnt_b = (const float*)d_in[12];
    const float* bnt_m = (const float*)d_in[13];
    const float* bnt_v = (const float*)d_in[14];
    float* out = (float*)d_out;

    prep_wt_kernel<<<256, 256>>>(conv1_w);
    prep_small_kernel<<<1, 64>>>(conv1_b, bn1_g, bn1_b, bn1_m, bn1_v,
                                 conv2_w, conv2_b, tconv_b, bnt_g, bnt_b, bnt_m, bnt_v);
    tvec_kernel<<<4096, 128>>>(x, tconv_w);
    dim3 g(16, 8);
    gemm_kernel<<<g, 256>>>(x);
    epi_kernel<<<512, 256>>>();
    softmax_kernel<<<512, 256>>>(out);
}